// round 15
// baseline (speedup 1.0000x reference)
#include <cuda_runtime.h>
#include <cuda_fp16.h>
#include <cstdint>

#define TGT 1024
#define SRC 1024
#define BSZb 4
#define EMB 1024
#define NH 16
#define HD 64

// -------- device scratch --------
__device__ __half g_qin[TGT * BSZb * EMB];          // query fp16
__device__ __half g_kin[SRC * BSZb * EMB];          // key fp16
__device__ __half g_w16[3 * EMB * EMB];             // in_proj_weight fp16
__device__ __half g_wo16[EMB * EMB];                // out_proj_weight fp16
__device__ __half g_q[BSZb * NH * TGT * HD];        // (b,h,t,d) scaled fp16
__device__ __half g_k[BSZb * NH * SRC * HD];        // (b,h,s,d) fp16
__device__ __half g_v[BSZb * NH * SRC * HD];        // (b,h,s,d) fp16
__device__ float  g_scores[(size_t)BSZb * NH * TGT * SRC]; // fp32 scores
__device__ __half g_p[(size_t)BSZb * NH * TGT * SRC];      // masked P fp16
__device__ __half g_ctx_h[TGT * BSZb * EMB];        // (t,b,e) fp16

__device__ __forceinline__ uint32_t h2u(__half2 h) {
    return *reinterpret_cast<uint32_t*>(&h);
}
__device__ __forceinline__ uint32_t smem_u32(const void* p) {
    uint32_t a;
    asm("{ .reg .u64 t; cvta.to.shared.u64 t, %1; cvt.u32.u64 %0, t; }" : "=r"(a) : "l"(p));
    return a;
}
__device__ __forceinline__ void mma16(float* d, uint32_t a0, uint32_t a1,
                                      uint32_t a2, uint32_t a3,
                                      uint32_t b0, uint32_t b1) {
    asm volatile(
        "mma.sync.aligned.m16n8k16.row.col.f32.f16.f16.f32 "
        "{%0,%1,%2,%3}, {%4,%5,%6,%7}, {%8,%9}, {%0,%1,%2,%3};"
        : "+f"(d[0]), "+f"(d[1]), "+f"(d[2]), "+f"(d[3])
        : "r"(a0), "r"(a1), "r"(a2), "r"(a3), "r"(b0), "r"(b1));
}
__device__ __forceinline__ void ldsm4(uint32_t* r, uint32_t addr) {
    asm volatile("ldmatrix.sync.aligned.m8n8.x4.shared.b16 {%0,%1,%2,%3}, [%4];"
        : "=r"(r[0]), "=r"(r[1]), "=r"(r[2]), "=r"(r[3]) : "r"(addr));
}
__device__ __forceinline__ void ldsm4t(uint32_t* r, uint32_t addr) {
    asm volatile("ldmatrix.sync.aligned.m8n8.x4.trans.shared.b16 {%0,%1,%2,%3}, [%4];"
        : "=r"(r[0]), "=r"(r[1]), "=r"(r[2]), "=r"(r[3]) : "r"(addr));
}
__device__ __forceinline__ void cp16(uint32_t dst, const void* src) {
    asm volatile("cp.async.cg.shared.global [%0], [%1], 16;" :: "r"(dst), "l"(src));
}
__device__ __forceinline__ void cp_commit() {
    asm volatile("cp.async.commit_group;" ::: "memory");
}
template <int N>
__device__ __forceinline__ void cp_wait() {
    asm volatile("cp.async.wait_group %0;" :: "n"(N) : "memory");
}

// ---------------------------------------------------------------------------
__global__ void __launch_bounds__(256)
cvt_kernel(const float4* __restrict__ in, uint2* __restrict__ out, int n4)
{
    int i = blockIdx.x * 256 + threadIdx.x;
    if (i < n4) {
        float4 v = in[i];
        out[i] = make_uint2(h2u(__floats2half2_rn(v.x, v.y)),
                            h2u(__floats2half2_rn(v.z, v.w)));
    }
}

// ===========================================================================
// fp16 GEMM, cp.async + ldmatrix, BK=64, 128B swizzled SMEM rows.
// MODE: 0=scores 1=Qproj 2=KVproj(N=2048) 4=PV(B=V, ldsm.trans) 5=outproj
// ===========================================================================
template <int BM, int BN, int WM, int WN, int MODE>
__global__ void __launch_bounds__(256, 2)
hgemm(const float* __restrict__ bias, float* __restrict__ C,
      int K, int lda, int ldb)
{
    constexpr bool BT = (MODE == 4);
    constexpr int WTM = BM / WM, WTN = BN / WN;
    constexpr int MT = WTM / 16, NT = WTN / 8;
    constexpr int ABYTES = BM * 128;
    constexpr int BROWS = BT ? 64 : BN;
    constexpr int BBYTES = BROWS * 128;

    extern __shared__ char sm[];
    const uint32_t sA = smem_u32(sm);
    const uint32_t sB = sA + 2 * ABYTES;

    const int z = blockIdx.z;
    const __half* Ah;
    const __half* Bh;
    if constexpr (MODE == 0) { Ah = g_q + (size_t)z * TGT * HD; Bh = g_k + (size_t)z * SRC * HD; }
    else if constexpr (MODE == 4) { Ah = g_p + (size_t)z * TGT * SRC; Bh = g_v + (size_t)z * SRC * HD; }
    else if constexpr (MODE == 5) { Ah = g_ctx_h; Bh = g_wo16; }
    else if constexpr (MODE == 1) { Ah = g_qin; Bh = g_w16; }
    else                          { Ah = g_kin; Bh = g_w16 + (size_t)EMB * EMB; }

    const int bm = blockIdx.y * BM;
    const int bn = blockIdx.x * BN;
    const int tid = threadIdx.x;
    const int lane = tid & 31;
    const int wid = tid >> 5;
    const int wm = wid / WN;
    const int wn = wid % WN;
    const int l4 = lane >> 2;
    const int lc = lane & 3;
    const int lr8 = ((lane >> 3) & 1) * 8 + (lane & 7);
    const int ghi = lane >> 4;

    float acc[MT][NT][4];
#pragma unroll
    for (int i = 0; i < MT; i++)
#pragma unroll
        for (int j = 0; j < NT; j++)
#pragma unroll
            for (int q = 0; q < 4; q++) acc[i][j][q] = 0.0f;

    const int NC = K / 64;

    auto loadA = [&](int buf, int ch) {
#pragma unroll
        for (int i = 0; i < BM * 8 / 256; i++) {
            int idx = tid + i * 256, r = idx >> 3, g = idx & 7;
            cp16(sA + buf * ABYTES + r * 128 + ((g ^ (r & 7)) << 4),
                 Ah + (size_t)(bm + r) * lda + ch * 64 + g * 8);
        }
    };
    auto loadB = [&](int buf, int ch) {
        if constexpr (BT) {
#pragma unroll
            for (int i = 0; i < 2; i++) {
                int idx = tid + i * 256, r = idx >> 3, g = idx & 7;
                cp16(sB + buf * BBYTES + r * 128 + ((g ^ (r & 7)) << 4),
                     Bh + (size_t)(ch * 64 + r) * ldb + g * 8);
            }
        } else {
#pragma unroll
            for (int i = 0; i < BROWS * 8 / 256; i++) {
                int idx = tid + i * 256, r = idx >> 3, g = idx & 7;
                cp16(sB + buf * BBYTES + r * 128 + ((g ^ (r & 7)) << 4),
                     Bh + (size_t)(bn + r) * ldb + ch * 64 + g * 8);
            }
        }
    };

    loadA(0, 0); loadB(0, 0);
    cp_commit();
    cp_wait<0>();
    __syncthreads();

    for (int ch = 0; ch < NC; ch++) {
        const int buf = ch & 1;
        if (ch + 1 < NC) {
            loadA(buf ^ 1, ch + 1);
            loadB(buf ^ 1, ch + 1);
            cp_commit();
        }
        const uint32_t bA = sA + buf * ABYTES;
        const uint32_t bB = sB + buf * BBYTES;

        if constexpr (BT) {
            uint32_t vfr[2][2][4];
#pragma unroll
            for (int ks32 = 0; ks32 < 2; ks32++)
#pragma unroll
                for (int jj = 0; jj < 2; jj++) {
                    int s = ks32 * 32 + lane;
                    int gidx = wn * 2 + jj;
                    ldsm4t(vfr[ks32][jj], bB + s * 128 + ((gidx ^ (s & 7)) << 4));
                }
#pragma unroll
            for (int ks = 0; ks < 4; ks++) {
                int kg = ks * 2 + ghi;
                int ks32 = ks >> 1, t = ks & 1;
#pragma unroll
                for (int mt = 0; mt < MT; mt++) {
                    int m = wm * WTM + mt * 16 + lr8;
                    uint32_t af[4];
                    ldsm4(af, bA + m * 128 + ((kg ^ (m & 7)) << 4));
#pragma unroll
                    for (int jj = 0; jj < 2; jj++)
                        mma16(acc[mt][jj], af[0], af[1], af[2], af[3],
                              vfr[ks32][jj][t * 2], vfr[ks32][jj][t * 2 + 1]);
                }
            }
        } else {
#pragma unroll
            for (int ks = 0; ks < 4; ks++) {
                int kg = ks * 2 + ghi;
                uint32_t bf[NT / 2][4];
#pragma unroll
                for (int np = 0; np < NT / 2; np++) {
                    int n = wn * WTN + np * 16 + lr8;
                    ldsm4(bf[np], bB + n * 128 + ((kg ^ (n & 7)) << 4));
                }
#pragma unroll
                for (int mt = 0; mt < MT; mt++) {
                    int m = wm * WTM + mt * 16 + lr8;
                    uint32_t af[4];
                    ldsm4(af, bA + m * 128 + ((kg ^ (m & 7)) << 4));
#pragma unroll
                    for (int np = 0; np < NT / 2; np++) {
                        mma16(acc[mt][2 * np],     af[0], af[1], af[2], af[3], bf[np][0], bf[np][2]);
                        mma16(acc[mt][2 * np + 1], af[0], af[1], af[2], af[3], bf[np][1], bf[np][3]);
                    }
                }
            }
        }

        if (ch + 1 < NC) {
            cp_wait<0>();
            __syncthreads();
        }
    }

    // ---- epilogue ----
#pragma unroll
    for (int mt = 0; mt < MT; mt++) {
#pragma unroll
        for (int nt = 0; nt < NT; nt++) {
            const int r0 = bm + wm * WTM + mt * 16 + l4;
            const int c0 = bn + wn * WTN + nt * 8 + 2 * lc;
            const float* a4 = acc[mt][nt];
#pragma unroll
            for (int half = 0; half < 2; half++) {
                const int r = r0 + half * 8;
                const float v0 = a4[half * 2 + 0];
                const float v1 = a4[half * 2 + 1];
                if constexpr (MODE == 0) {
                    *(float2*)(g_scores + (size_t)z * TGT * SRC + (size_t)r * SRC + c0) =
                        make_float2(v0, v1);
                } else if constexpr (MODE == 4) {
                    int b = z >> 4, h = z & 15;
                    *(__half2*)(g_ctx_h + ((size_t)r * BSZb + b) * EMB + h * 64 + c0) =
                        __floats2half2_rn(v0, v1);
                } else if constexpr (MODE == 5) {
                    *(float2*)(C + (size_t)r * EMB + c0) =
                        make_float2(v0 + bias[c0], v1 + bias[c0 + 1]);
                } else if constexpr (MODE == 1) {
                    int t = r >> 2, b = r & 3, hh = c0 >> 6, d = c0 & 63;
                    *(__half2*)(g_q + (((size_t)(b * NH + hh)) * TGT + t) * HD + d) =
                        __floats2half2_rn((v0 + bias[c0]) * 0.125f,
                                          (v1 + bias[c0 + 1]) * 0.125f);
                } else { // MODE == 2: merged K/V projection, N=2048
                    int s = r >> 2, b = r & 3;
                    int cc = c0 & 1023, hh = cc >> 6, d = cc & 63;
                    __half* dst = (c0 < 1024) ? g_k : g_v;
                    *(__half2*)(dst + (((size_t)(b * NH + hh)) * SRC + s) * HD + d) =
                        __floats2half2_rn(v0 + bias[c0], v1 + bias[c0 + 1]);
                }
            }
        }
    }
}

// ---------------------------------------------------------------------------
// Warp-per-head softmax: 512 threads, warp h owns head h's row (t,b).
// No block barriers in the head loop; avg via SMEM float atomics.
// ---------------------------------------------------------------------------
__global__ void __launch_bounds__(512)
softmax_mask_avg_kernel(const float* __restrict__ hard, float* __restrict__ avg_out)
{
    const int t = blockIdx.x;
    const int b = blockIdx.y;
    const int tid = threadIdx.x;
    const int lane = tid & 31;
    const int h = tid >> 5;         // warp = head

    __shared__ float s_avg[SRC];
    __shared__ float s_mask[SRC];

    // stage mask + zero avg (1024 floats each, 512 threads)
    {
        const float4* mrow = (const float4*)(hard + ((size_t)b * TGT + t) * SRC);
        float4 m0 = mrow[tid >> 1];
        // each pair of threads splits one float4: thread even -> .x.y, odd -> .z.w
        int c = (tid >> 1) * 4 + (tid & 1) * 2;
        s_mask[c] = (tid & 1) ? m0.z : m0.x;
        s_mask[c + 1] = (tid & 1) ? m0.w : m0.y;
        s_avg[tid] = 0.f;
        s_avg[tid + 512] = 0.f;
    }
    __syncthreads();

    const size_t roff = ((size_t)(b * NH + h) * TGT + t) * SRC;
    const float4* srow = (const float4*)(g_scores + roff);

    // load 32 scores per lane: float4 at col j*128 + lane*4
    float4 v[8];
#pragma unroll
    for (int j = 0; j < 8; j++) v[j] = srow[j * 32 + lane];

    float m = -1e30f;
#pragma unroll
    for (int j = 0; j < 8; j++)
        m = fmaxf(m, fmaxf(fmaxf(v[j].x, v[j].y), fmaxf(v[j].z, v[j].w)));
#pragma unroll
    for (int o = 16; o; o >>= 1) m = fmaxf(m, __shfl_xor_sync(0xffffffffu, m, o));

    float s = 0.f;
#pragma unroll
    for (int j = 0; j < 8; j++) {
        v[j].x = __expf(v[j].x - m); v[j].y = __expf(v[j].y - m);
        v[j].z = __expf(v[j].z - m); v[j].w = __expf(v[j].w - m);
        s += v[j].x + v[j].y + v[j].z + v[j].w;
    }
#pragma unroll
    for (int o = 16; o; o >>= 1) s += __shfl_xor_sync(0xffffffffu, s, o);
    const float inv = 1.0f / s;

    uint2* prow = (uint2*)(g_p + roff);
#pragma unroll
    for (int j = 0; j < 8; j++) {
        const int c = j * 128 + lane * 4;
        float p0 = v[j].x * inv * s_mask[c];
        float p1 = v[j].y * inv * s_mask[c + 1];
        float p2 = v[j].z * inv * s_mask[c + 2];
        float p3 = v[j].w * inv * s_mask[c + 3];
        prow[j * 32 + lane] = make_uint2(h2u(__floats2half2_rn(p0, p1)),
                                         h2u(__floats2half2_rn(p2, p3)));
        atomicAdd(&s_avg[c], p0);
        atomicAdd(&s_avg[c + 1], p1);
        atomicAdd(&s_avg[c + 2], p2);
        atomicAdd(&s_avg[c + 3], p3);
    }
    __syncthreads();

    float* arow = avg_out + ((size_t)b * TGT + t) * SRC;
    arow[tid] = s_avg[tid] * (1.0f / NH);
    arow[tid + 512] = s_avg[tid + 512] * (1.0f / NH);
}

// ---------------------------------------------------------------------------
extern "C" void kernel_launch(void* const* d_in, const int* in_sizes, int n_in,
                              void* d_out, int out_size)
{
    const float* query = (const float*)d_in[0];
    const float* key   = (const float*)d_in[1];
    const float* hard  = (const float*)d_in[2];
    const float* W     = (const float*)d_in[3];
    const float* bias  = (const float*)d_in[4];
    const float* Wo    = (const float*)d_in[5];
    const float* bo    = (const float*)d_in[6];
    float* out = (float*)d_out;
    float* avg_out = out + (size_t)TGT * BSZb * EMB;

    constexpr int SM_BIG = 2 * 128 * 128 + 2 * 128 * 128;   // 65536
    constexpr int SM_PV  = 2 * 128 * 128 + 2 * 64 * 128;    // 49152

    cudaFuncSetAttribute(hgemm<128, 128, 2, 4, 0>, cudaFuncAttributeMaxDynamicSharedMemorySize, SM_BIG);
    cudaFuncSetAttribute(hgemm<128, 128, 2, 4, 1>, cudaFuncAttributeMaxDynamicSharedMemorySize, SM_BIG);
    cudaFuncSetAttribute(hgemm<128, 128, 2, 4, 2>, cudaFuncAttributeMaxDynamicSharedMemorySize, SM_BIG);
    cudaFuncSetAttribute(hgemm<128, 64, 2, 4, 4>,  cudaFuncAttributeMaxDynamicSharedMemorySize, SM_PV);
    cudaFuncSetAttribute(hgemm<128, 128, 2, 4, 5>, cudaFuncAttributeMaxDynamicSharedMemorySize, SM_BIG);

    // 0: fp32 -> fp16 conversions
    {
        __half* p;
        int n4;
        cudaGetSymbolAddress((void**)&p, g_qin);
        n4 = TGT * BSZb * EMB / 4;
        cvt_kernel<<<(n4 + 255) / 256, 256>>>((const float4*)query, (uint2*)p, n4);
        cudaGetSymbolAddress((void**)&p, g_kin);
        cvt_kernel<<<(n4 + 255) / 256, 256>>>((const float4*)key, (uint2*)p, n4);
        cudaGetSymbolAddress((void**)&p, g_w16);
        n4 = 3 * EMB * EMB / 4;
        cvt_kernel<<<(n4 + 255) / 256, 256>>>((const float4*)W, (uint2*)p, n4);
        cudaGetSymbolAddress((void**)&p, g_wo16);
        n4 = EMB * EMB / 4;
        cvt_kernel<<<(n4 + 255) / 256, 256>>>((const float4*)Wo, (uint2*)p, n4);
    }

    // 1: Q projection (M=4096, N=1024, K=1024)
    {
        dim3 grid(EMB / 128, TGT * BSZb / 128);
        hgemm<128, 128, 2, 4, 1><<<grid, 256, SM_BIG>>>(bias, nullptr, EMB, EMB, EMB);
    }
    // 2: merged K+V projection (M=4096, N=2048, K=1024)
    {
        dim3 grid(2 * EMB / 128, TGT * BSZb / 128);
        hgemm<128, 128, 2, 4, 2><<<grid, 256, SM_BIG>>>(bias + EMB, nullptr, EMB, EMB, EMB);
    }
    // 3: scores = Q K^T per (b,h)
    {
        dim3 grid(SRC / 128, TGT / 128, BSZb * NH);
        hgemm<128, 128, 2, 4, 0><<<grid, 256, SM_BIG>>>(nullptr, nullptr, HD, HD, HD);
    }
    // 4: softmax + mask + head-average
    {
        dim3 grid(TGT, BSZb);
        softmax_mask_avg_kernel<<<grid, 512>>>(hard, avg_out);
    }
    // 5: ctx = P V per (b,h)
    {
        dim3 grid(1, TGT / 128, BSZb * NH);
        hgemm<128, 64, 2, 4, 4><<<grid, 256, SM_PV>>>(nullptr, nullptr, SRC, SRC, HD);
    }
    // 6: out projection
    {
        dim3 grid(EMB / 128, TGT * BSZb / 128);
        hgemm<128, 128, 2, 4, 5><<<grid, 256, SM_BIG>>>(bo, out, EMB, EMB, EMB);
    }
}

// round 16
// speedup vs baseline: 1.6978x; 1.6978x over previous
#include <cuda_runtime.h>
#include <cuda_fp16.h>
#include <cstdint>

#define TGT 1024
#define SRC 1024
#define BSZb 4
#define EMB 1024
#define NH 16
#define HD 64

// -------- device scratch --------
__device__ __half g_qin[TGT * BSZb * EMB];
__device__ __half g_kin[SRC * BSZb * EMB];
__device__ __half g_w16[3 * EMB * EMB];
__device__ __half g_wo16[EMB * EMB];
__device__ __half g_q[BSZb * NH * TGT * HD];        // (b,h,t,d) scaled
__device__ __half g_k[BSZb * NH * SRC * HD];        // (b,h,s,d)
__device__ __half g_v[BSZb * NH * SRC * HD];        // (b,h,s,d)
__device__ __half g_p[(size_t)BSZb * NH * TGT * SRC]; // masked P fp16
__device__ __half g_ctx_h[TGT * BSZb * EMB];        // (t,b,e)

__device__ __forceinline__ uint32_t h2u(__half2 h) {
    return *reinterpret_cast<uint32_t*>(&h);
}
__device__ __forceinline__ uint32_t smem_u32(const void* p) {
    uint32_t a;
    asm("{ .reg .u64 t; cvta.to.shared.u64 t, %1; cvt.u32.u64 %0, t; }" : "=r"(a) : "l"(p));
    return a;
}
__device__ __forceinline__ void mma16(float* d, uint32_t a0, uint32_t a1,
                                      uint32_t a2, uint32_t a3,
                                      uint32_t b0, uint32_t b1) {
    asm volatile(
        "mma.sync.aligned.m16n8k16.row.col.f32.f16.f16.f32 "
        "{%0,%1,%2,%3}, {%4,%5,%6,%7}, {%8,%9}, {%0,%1,%2,%3};"
        : "+f"(d[0]), "+f"(d[1]), "+f"(d[2]), "+f"(d[3])
        : "r"(a0), "r"(a1), "r"(a2), "r"(a3), "r"(b0), "r"(b1));
}
__device__ __forceinline__ void ldsm4(uint32_t* r, uint32_t addr) {
    asm volatile("ldmatrix.sync.aligned.m8n8.x4.shared.b16 {%0,%1,%2,%3}, [%4];"
        : "=r"(r[0]), "=r"(r[1]), "=r"(r[2]), "=r"(r[3]) : "r"(addr));
}
__device__ __forceinline__ void ldsm4t(uint32_t* r, uint32_t addr) {
    asm volatile("ldmatrix.sync.aligned.m8n8.x4.trans.shared.b16 {%0,%1,%2,%3}, [%4];"
        : "=r"(r[0]), "=r"(r[1]), "=r"(r[2]), "=r"(r[3]) : "r"(addr));
}
__device__ __forceinline__ void cp16(uint32_t dst, const void* src) {
    asm volatile("cp.async.cg.shared.global [%0], [%1], 16;" :: "r"(dst), "l"(src));
}
__device__ __forceinline__ void cp_commit() {
    asm volatile("cp.async.commit_group;" ::: "memory");
}
template <int N>
__device__ __forceinline__ void cp_wait() {
    asm volatile("cp.async.wait_group %0;" :: "n"(N) : "memory");
}

// ---------------------------------------------------------------------------
// single fused fp32->fp16 conversion pass over all four tensors
// ---------------------------------------------------------------------------
#define CVT_Q4  1048576                // TGT*BSZb*EMB/4
#define CVT_K4  2097152
#define CVT_W4  2883584                // + 3*EMB*EMB/4
#define CVT_T4  3145728                // + EMB*EMB/4
__global__ void __launch_bounds__(256)
cvt_all_kernel(const float4* __restrict__ q, const float4* __restrict__ k,
               const float4* __restrict__ w, const float4* __restrict__ wo)
{
    int i = blockIdx.x * 256 + threadIdx.x;
    const float4* src;
    uint2* dst;
    int off;
    if (i < CVT_Q4)      { src = q;  dst = (uint2*)g_qin;  off = i; }
    else if (i < CVT_K4) { src = k;  dst = (uint2*)g_kin;  off = i - CVT_Q4; }
    else if (i < CVT_W4) { src = w;  dst = (uint2*)g_w16;  off = i - CVT_K4; }
    else                 { src = wo; dst = (uint2*)g_wo16; off = i - CVT_W4; }
    float4 v = src[off];
    dst[off] = make_uint2(h2u(__floats2half2_rn(v.x, v.y)),
                          h2u(__floats2half2_rn(v.z, v.w)));
}

// ===========================================================================
// Fused scores + softmax + mask: CTA = (b,h, 32 t-rows).
//   Q frags in regs, K streamed (cp.async dbuf), scores -> 128 KB SMEM fp32,
//   warp-per-4-rows softmax, multiply gmem mask, write P fp16 to g_p.
// ===========================================================================
#define FS_SC 0                       // 32 x 1024 fp32, swizzled   131072
#define FS_Q  131072                  // 32 x 64 fp16, swizzled       4096
#define FS_K0 135168                  // 128 x 64 fp16, swizzled     16384
#define FS_K1 151552
#define SMEM_FS 167936

__device__ __forceinline__ int fs_sc(int r, int w) {
    return FS_SC + (r << 12) + ((((w >> 2) ^ (r & 7)) << 4) | ((w & 3) << 2));
}

__global__ void __launch_bounds__(256)
fused_scores_softmax(const float* __restrict__ hard)
{
    extern __shared__ char sm[];
    const uint32_t sb = smem_u32(sm);
    const int bh = blockIdx.y;             // b*NH + h
    const int b = bh >> 4;
    const int t0 = blockIdx.x * 32;
    const int tid = threadIdx.x;
    const int lane = tid & 31;
    const int w = tid >> 5;                // 0..7
    const int wm = w >> 2;                 // 0..1 (t halves)
    const int wn = w & 3;                  // 0..3 (s quarters of 128)
    const int l4 = lane >> 2;
    const int lc = lane & 3;
    const int lr8 = ((lane >> 3) & 1) * 8 + (lane & 7);
    const int ghi = lane >> 4;

    const __half* qg = g_q + (size_t)bh * TGT * HD + (size_t)t0 * HD;
    const __half* kg = g_k + (size_t)bh * SRC * HD;

    // ---- cp.async: Q tile (32x64) + K chunk 0 (128x64) ----
    {
        int r = tid >> 3, g = tid & 7;
        cp16(sb + FS_Q + r * 128 + ((g ^ (r & 7)) << 4), qg + (size_t)r * HD + g * 8);
    }
#pragma unroll
    for (int i = 0; i < 4; i++) {
        int idx = tid + i * 256, r = idx >> 3, g = idx & 7;
        cp16(sb + FS_K0 + r * 128 + ((g ^ (r & 7)) << 4), kg + (size_t)r * HD + g * 8);
    }
    cp_commit();
    cp_wait<0>();
    __syncthreads();

    // ---- Q fragments (rows wm*16 + lr8), one per k16 step ----
    uint32_t qf[4][4];
#pragma unroll
    for (int ks = 0; ks < 4; ks++) {
        int kg2 = ks * 2 + ghi;
        int r = wm * 16 + lr8;
        ldsm4(qf[ks], sb + FS_Q + r * 128 + ((kg2 ^ (r & 7)) << 4));
    }

    // ---- phase A: 8 s-chunks of 128 ----
#pragma unroll 1
    for (int ch = 0; ch < 8; ch++) {
        const uint32_t kb = sb + ((ch & 1) ? FS_K1 : FS_K0);
        if (ch < 7) {
            const __half* kgc = kg + (size_t)(ch + 1) * 128 * HD;
            const uint32_t nb = sb + ((ch & 1) ? FS_K0 : FS_K1);
#pragma unroll
            for (int i = 0; i < 4; i++) {
                int idx = tid + i * 256, r = idx >> 3, g = idx & 7;
                cp16(nb + r * 128 + ((g ^ (r & 7)) << 4), kgc + (size_t)r * HD + g * 8);
            }
            cp_commit();
        }

        float acc[4][4];
#pragma unroll
        for (int nt = 0; nt < 4; nt++)
#pragma unroll
            for (int q = 0; q < 4; q++) acc[nt][q] = 0.f;

#pragma unroll
        for (int ks = 0; ks < 4; ks++) {
            int kg2 = ks * 2 + ghi;
            uint32_t bf[2][4];
#pragma unroll
            for (int np = 0; np < 2; np++) {
                int n = wn * 32 + np * 16 + lr8;
                ldsm4(bf[np], kb + n * 128 + ((kg2 ^ (n & 7)) << 4));
            }
#pragma unroll
            for (int np = 0; np < 2; np++) {
                mma16(acc[2 * np],     qf[ks][0], qf[ks][1], qf[ks][2], qf[ks][3],
                      bf[np][0], bf[np][2]);
                mma16(acc[2 * np + 1], qf[ks][0], qf[ks][1], qf[ks][2], qf[ks][3],
                      bf[np][1], bf[np][3]);
            }
        }

        // store scores into sc
#pragma unroll
        for (int nt = 0; nt < 4; nt++) {
            int wi = ch * 128 + wn * 32 + nt * 8 + 2 * lc;
            int r = wm * 16 + l4;
            *(float2*)(sm + fs_sc(r, wi)) = make_float2(acc[nt][0], acc[nt][1]);
            *(float2*)(sm + fs_sc(r + 8, wi)) = make_float2(acc[nt][2], acc[nt][3]);
        }

        if (ch < 7) {
            cp_wait<0>();
            __syncthreads();
        }
    }
    __syncthreads();

    // ---- softmax + mask + P write: warp w owns rows 4w..4w+3 ----
#pragma unroll 1
    for (int rr = 0; rr < 4; rr++) {
        const int r = w * 4 + rr;
        float4 x[8];
#pragma unroll
        for (int p = 0; p < 8; p++)
            x[p] = *(float4*)(sm + fs_sc(r, p * 128 + lane * 4));

        float m = -1e30f;
#pragma unroll
        for (int p = 0; p < 8; p++)
            m = fmaxf(m, fmaxf(fmaxf(x[p].x, x[p].y), fmaxf(x[p].z, x[p].w)));
#pragma unroll
        for (int o = 16; o; o >>= 1) m = fmaxf(m, __shfl_xor_sync(0xffffffffu, m, o));

        float s = 0.f;
#pragma unroll
        for (int p = 0; p < 8; p++) {
            x[p].x = __expf(x[p].x - m); x[p].y = __expf(x[p].y - m);
            x[p].z = __expf(x[p].z - m); x[p].w = __expf(x[p].w - m);
            s += x[p].x + x[p].y + x[p].z + x[p].w;
        }
#pragma unroll
        for (int o = 16; o; o >>= 1) s += __shfl_xor_sync(0xffffffffu, s, o);
        const float inv = 1.0f / s;

        const float4* mrow = (const float4*)(hard + ((size_t)b * TGT + t0 + r) * SRC);
        uint2* prow = (uint2*)(g_p + ((size_t)bh * TGT + t0 + r) * SRC);
#pragma unroll
        for (int p = 0; p < 8; p++) {
            float4 mk = mrow[p * 32 + lane];
            float p0 = x[p].x * inv * mk.x;
            float p1 = x[p].y * inv * mk.y;
            float p2 = x[p].z * inv * mk.z;
            float p3 = x[p].w * inv * mk.w;
            prow[p * 32 + lane] = make_uint2(h2u(__floats2half2_rn(p0, p1)),
                                             h2u(__floats2half2_rn(p2, p3)));
        }
    }
}

// ---------------------------------------------------------------------------
// avg_weights = sum_h P / NH   (reads g_p fp16, writes fp32)
// ---------------------------------------------------------------------------
__global__ void __launch_bounds__(256)
avg_kernel(float* __restrict__ avg_out)
{
    const int t = blockIdx.x;
    const int b = blockIdx.y;
    const int c = threadIdx.x * 4;

    float s0 = 0.f, s1 = 0.f, s2 = 0.f, s3 = 0.f;
#pragma unroll
    for (int h = 0; h < NH; h++) {
        uint2 u = *(const uint2*)(g_p + ((size_t)(b * NH + h) * TGT + t) * SRC + c);
        float2 lo = __half22float2(*reinterpret_cast<__half2*>(&u.x));
        float2 hi = __half22float2(*reinterpret_cast<__half2*>(&u.y));
        s0 += lo.x; s1 += lo.y; s2 += hi.x; s3 += hi.y;
    }
    float4 r = { s0 * (1.0f / NH), s1 * (1.0f / NH),
                 s2 * (1.0f / NH), s3 * (1.0f / NH) };
    *(float4*)(avg_out + ((size_t)b * TGT + t) * SRC + c) = r;
}

// ===========================================================================
// fp16 GEMM (R12-proven): cp.async + ldmatrix, BK=64, swizzled SMEM.
// MODE: 1=Qproj 2=Kproj 3=Vproj 4=PV(B=V, ldsm.trans) 5=outproj
// ===========================================================================
template <int BM, int BN, int WM, int WN, int MODE>
__global__ void __launch_bounds__(256)
hgemm(const float* __restrict__ bias, float* __restrict__ C,
      int K, int lda, int ldb)
{
    constexpr bool BT = (MODE == 4);
    constexpr int WTM = BM / WM, WTN = BN / WN;
    constexpr int MT = WTM / 16, NT = WTN / 8;
    constexpr int ABYTES = BM * 128;
    constexpr int BROWS = BT ? 64 : BN;
    constexpr int BBYTES = BROWS * 128;

    extern __shared__ char sm[];
    const uint32_t sA = smem_u32(sm);
    const uint32_t sB = sA + 2 * ABYTES;

    const int z = blockIdx.z;
    const __half* Ah;
    const __half* Bh;
    if constexpr (MODE == 4) { Ah = g_p + (size_t)z * TGT * SRC; Bh = g_v + (size_t)z * SRC * HD; }
    else if constexpr (MODE == 5) { Ah = g_ctx_h; Bh = g_wo16; }
    else if constexpr (MODE == 1) { Ah = g_qin; Bh = g_w16; }
    else if constexpr (MODE == 2) { Ah = g_kin; Bh = g_w16 + (size_t)EMB * EMB; }
    else                          { Ah = g_kin; Bh = g_w16 + (size_t)2 * EMB * EMB; }

    const int bm = blockIdx.y * BM;
    const int bn = blockIdx.x * BN;
    const int tid = threadIdx.x;
    const int lane = tid & 31;
    const int wid = tid >> 5;
    const int wm = wid / WN;
    const int wn = wid % WN;
    const int l4 = lane >> 2;
    const int lc = lane & 3;
    const int lr8 = ((lane >> 3) & 1) * 8 + (lane & 7);
    const int ghi = lane >> 4;

    float acc[MT][NT][4];
#pragma unroll
    for (int i = 0; i < MT; i++)
#pragma unroll
        for (int j = 0; j < NT; j++)
#pragma unroll
            for (int q = 0; q < 4; q++) acc[i][j][q] = 0.0f;

    const int NC = K / 64;

    auto loadA = [&](int buf, int ch) {
#pragma unroll
        for (int i = 0; i < BM * 8 / 256; i++) {
            int idx = tid + i * 256, r = idx >> 3, g = idx & 7;
            cp16(sA + buf * ABYTES + r * 128 + ((g ^ (r & 7)) << 4),
                 Ah + (size_t)(bm + r) * lda + ch * 64 + g * 8);
        }
    };
    auto loadB = [&](int buf, int ch) {
        if constexpr (BT) {
#pragma unroll
            for (int i = 0; i < 2; i++) {
                int idx = tid + i * 256, r = idx >> 3, g = idx & 7;
                cp16(sB + buf * BBYTES + r * 128 + ((g ^ (r & 7)) << 4),
                     Bh + (size_t)(ch * 64 + r) * ldb + g * 8);
            }
        } else {
#pragma unroll
            for (int i = 0; i < BROWS * 8 / 256; i++) {
                int idx = tid + i * 256, r = idx >> 3, g = idx & 7;
                cp16(sB + buf * BBYTES + r * 128 + ((g ^ (r & 7)) << 4),
                     Bh + (size_t)(bn + r) * ldb + ch * 64 + g * 8);
            }
        }
    };

    loadA(0, 0); loadB(0, 0);
    cp_commit();
    cp_wait<0>();
    __syncthreads();

    for (int ch = 0; ch < NC; ch++) {
        const int buf = ch & 1;
        if (ch + 1 < NC) {
            loadA(buf ^ 1, ch + 1);
            loadB(buf ^ 1, ch + 1);
            cp_commit();
        }
        const uint32_t bA = sA + buf * ABYTES;
        const uint32_t bB = sB + buf * BBYTES;

        if constexpr (BT) {
            uint32_t vfr[2][2][4];
#pragma unroll
            for (int ks32 = 0; ks32 < 2; ks32++)
#pragma unroll
                for (int jj = 0; jj < 2; jj++) {
                    int s = ks32 * 32 + lane;
                    int gidx = wn * 2 + jj;
                    ldsm4t(vfr[ks32][jj], bB + s * 128 + ((gidx ^ (s & 7)) << 4));
                }
#pragma unroll
            for (int ks = 0; ks < 4; ks++) {
                int kg = ks * 2 + ghi;
                int ks32 = ks >> 1, t = ks & 1;
#pragma unroll
                for (int mt = 0; mt < MT; mt++) {
                    int m = wm * WTM + mt * 16 + lr8;
                    uint32_t af[4];
                    ldsm4(af, bA + m * 128 + ((kg ^ (m & 7)) << 4));
#pragma unroll
                    for (int jj = 0; jj < 2; jj++)
                        mma16(acc[mt][jj], af[0], af[1], af[2], af[3],
                              vfr[ks32][jj][t * 2], vfr[ks32][jj][t * 2 + 1]);
                }
            }
        } else {
#pragma unroll
            for (int ks = 0; ks < 4; ks++) {
                int kg = ks * 2 + ghi;
                uint32_t bf[NT / 2][4];
#pragma unroll
                for (int np = 0; np < NT / 2; np++) {
                    int n = wn * WTN + np * 16 + lr8;
                    ldsm4(bf[np], bB + n * 128 + ((kg ^ (n & 7)) << 4));
                }
#pragma unroll
                for (int mt = 0; mt < MT; mt++) {
                    int m = wm * WTM + mt * 16 + lr8;
                    uint32_t af[4];
                    ldsm4(af, bA + m * 128 + ((kg ^ (m & 7)) << 4));
#pragma unroll
                    for (int np = 0; np < NT / 2; np++) {
                        mma16(acc[mt][2 * np],     af[0], af[1], af[2], af[3], bf[np][0], bf[np][2]);
                        mma16(acc[mt][2 * np + 1], af[0], af[1], af[2], af[3], bf[np][1], bf[np][3]);
                    }
                }
            }
        }

        if (ch + 1 < NC) {
            cp_wait<0>();
            __syncthreads();
        }
    }

    // ---- epilogue ----
#pragma unroll
    for (int mt = 0; mt < MT; mt++) {
#pragma unroll
        for (int nt = 0; nt < NT; nt++) {
            const int r0 = bm + wm * WTM + mt * 16 + l4;
            const int c0 = bn + wn * WTN + nt * 8 + 2 * lc;
            const float* a4 = acc[mt][nt];
#pragma unroll
            for (int half = 0; half < 2; half++) {
                const int r = r0 + half * 8;
                const float v0 = a4[half * 2 + 0];
                const float v1 = a4[half * 2 + 1];
                if constexpr (MODE == 4) {
                    int b = z >> 4, h = z & 15;
                    *(__half2*)(g_ctx_h + ((size_t)r * BSZb + b) * EMB + h * 64 + c0) =
                        __floats2half2_rn(v0, v1);
                } else if constexpr (MODE == 5) {
                    *(float2*)(C + (size_t)r * EMB + c0) =
                        make_float2(v0 + bias[c0], v1 + bias[c0 + 1]);
                } else if constexpr (MODE == 1) {
                    int t = r >> 2, b = r & 3, hh = c0 >> 6, d = c0 & 63;
                    *(__half2*)(g_q + (((size_t)(b * NH + hh)) * TGT + t) * HD + d) =
                        __floats2half2_rn((v0 + bias[c0]) * 0.125f,
                                          (v1 + bias[c0 + 1]) * 0.125f);
                } else if constexpr (MODE == 2) {
                    int s = r >> 2, b = r & 3, hh = c0 >> 6, d = c0 & 63;
                    *(__half2*)(g_k + (((size_t)(b * NH + hh)) * SRC + s) * HD + d) =
                        __floats2half2_rn(v0 + bias[c0], v1 + bias[c0 + 1]);
                } else { // MODE == 3
                    int s = r >> 2, b = r & 3, hh = c0 >> 6, d = c0 & 63;
                    *(__half2*)(g_v + (((size_t)(b * NH + hh)) * SRC + s) * HD + d) =
                        __floats2half2_rn(v0 + bias[c0], v1 + bias[c0 + 1]);
                }
            }
        }
    }
}

// ---------------------------------------------------------------------------
extern "C" void kernel_launch(void* const* d_in, const int* in_sizes, int n_in,
                              void* d_out, int out_size)
{
    const float* query = (const float*)d_in[0];
    const float* key   = (const float*)d_in[1];
    const float* hard  = (const float*)d_in[2];
    const float* W     = (const float*)d_in[3];
    const float* bias  = (const float*)d_in[4];
    const float* Wo    = (const float*)d_in[5];
    const float* bo    = (const float*)d_in[6];
    float* out = (float*)d_out;
    float* avg_out = out + (size_t)TGT * BSZb * EMB;

    constexpr int SM_BIG = 2 * 128 * 128 + 2 * 128 * 128;   // 65536
    constexpr int SM_PV  = 2 * 128 * 128 + 2 * 64 * 128;    // 49152

    cudaFuncSetAttribute(hgemm<128, 128, 2, 4, 1>, cudaFuncAttributeMaxDynamicSharedMemorySize, SM_BIG);
    cudaFuncSetAttribute(hgemm<128, 128, 2, 4, 2>, cudaFuncAttributeMaxDynamicSharedMemorySize, SM_BIG);
    cudaFuncSetAttribute(hgemm<128, 128, 2, 4, 3>, cudaFuncAttributeMaxDynamicSharedMemorySize, SM_BIG);
    cudaFuncSetAttribute(hgemm<128, 64, 2, 4, 4>,  cudaFuncAttributeMaxDynamicSharedMemorySize, SM_PV);
    cudaFuncSetAttribute(hgemm<128, 128, 2, 4, 5>, cudaFuncAttributeMaxDynamicSharedMemorySize, SM_BIG);
    cudaFuncSetAttribute(fused_scores_softmax, cudaFuncAttributeMaxDynamicSharedMemorySize, SMEM_FS);

    // 0: fused fp32->fp16 conversion
    cvt_all_kernel<<<CVT_T4 / 256, 256>>>((const float4*)query, (const float4*)key,
                                          (const float4*)W, (const float4*)Wo);

    // 1..3: Q/K/V projections (M=4096, N=1024, K=1024)
    {
        dim3 grid(EMB / 128, TGT * BSZb / 128);
        hgemm<128, 128, 2, 4, 1><<<grid, 256, SM_BIG>>>(bias, nullptr, EMB, EMB, EMB);
        hgemm<128, 128, 2, 4, 2><<<grid, 256, SM_BIG>>>(bias + EMB, nullptr, EMB, EMB, EMB);
        hgemm<128, 128, 2, 4, 3><<<grid, 256, SM_BIG>>>(bias + 2 * EMB, nullptr, EMB, EMB, EMB);
    }
    // 4: fused scores + softmax + mask -> g_p
    {
        dim3 grid(TGT / 32, BSZb * NH);
        fused_scores_softmax<<<grid, 256, SMEM_FS>>>(hard);
    }
    // 5: avg_weights = head-average of P
    {
        dim3 grid(TGT, BSZb);
        avg_kernel<<<grid, 256>>>(avg_out);
    }
    // 6: ctx = P V per (b,h)
    {
        dim3 grid(1, TGT / 128, BSZb * NH);
        hgemm<128, 64, 2, 4, 4><<<grid, 256, SM_PV>>>(nullptr, nullptr, SRC, SRC, HD);
    }
    // 7: out projection
    {
        dim3 grid(EMB / 128, TGT * BSZb / 128);
        hgemm<128, 128, 2, 4, 5><<<grid, 256, SM_BIG>>>(bo, out, EMB, EMB, EMB);
    }
}